// round 15
// baseline (speedup 1.0000x reference)
#include <cuda_runtime.h>
#include <mma.h>
#include <math.h>

using namespace nvcuda;

#define N_NODES 20000
#define N_PAD   20032
#define D 128
#define E_EDGES 640000

// ---- scratch (static device globals; zero-initialized at load, no allocation) ----
// NOTE: these are ONLY referenced from device code. Passing them as kernel
// arguments from host code yields the host shadow address (silently readable
// as zeros on GB300 via ATS) — that was the R8-R11 bug.
__device__ float g_h[N_PAD * D];                       // layer-1 output (f32 skip path)
__device__ float g_hhi[N_PAD * D],   g_hlo[N_PAD * D]; // layer-1 output hi/lo (layer2 A)
__device__ float g_agghi[N_PAD * D], g_agglo[N_PAD * D];
__device__ float g_xhi[N_PAD * D],   g_xlo[N_PAD * D];
__device__ float g_Wrelhi[D * D],  g_Wrello[D * D];
__device__ float g_Wroothi[D * D], g_Wrootlo[D * D];
__device__ float g_linhi[D * D],   g_linlo[D * D];
__device__ int   g_cnt[N_NODES];
__device__ int   g_off[N_NODES];
__device__ int   g_cur[N_NODES];
__device__ int2  g_edges[E_EDGES];

__device__ __forceinline__ float gelu_exact(float v) {
    return 0.5f * v * (1.0f + erff(v * 0.70710678118654752f));
}
__device__ __forceinline__ float tf32_hi(float v) {
    return __uint_as_float(__float_as_uint(v) & 0xFFFFE000u);
}
__device__ __forceinline__ void split4(float4 v, float4& h, float4& l) {
    h.x = tf32_hi(v.x); l.x = v.x - h.x;
    h.y = tf32_hi(v.y); l.y = v.y - h.y;
    h.z = tf32_hi(v.z); l.z = v.z - h.z;
    h.w = tf32_hi(v.w); l.w = v.w - h.w;
}

// ---------------- prep: zero hist + split weights and x into hi/lo ----------------
__global__ void k_prep(const float* __restrict__ x,
                       const float* __restrict__ Wrel, const float* __restrict__ Wroot,
                       const float* __restrict__ linW) {
    int bid = blockIdx.x, tid = threadIdx.x;
    if (bid < 79) {
        int i = bid * 256 + tid;
        if (i < N_NODES) g_cnt[i] = 0;
    } else if (bid < 79 + 48) {
        int i = (bid - 79) * 256 + tid;    // 0..12287 float4 units over 3 matrices
        int m = i >> 12;                   // 4096 float4 per 128x128 matrix
        int r = i & 4095;
        const float* src = (m == 0) ? Wrel : ((m == 1) ? Wroot : linW);
        float* dh = (m == 0) ? g_Wrelhi : ((m == 1) ? g_Wroothi : g_linhi);
        float* dl = (m == 0) ? g_Wrello : ((m == 1) ? g_Wrootlo : g_linlo);
        float4 v = reinterpret_cast<const float4*>(src)[r];
        float4 h, l; split4(v, h, l);
        reinterpret_cast<float4*>(dh)[r] = h;
        reinterpret_cast<float4*>(dl)[r] = l;
    } else {
        int j = (bid - 127) * 256 + tid;   // 0..639999 float4 units of x
        float4 v = reinterpret_cast<const float4*>(x)[j];
        float4 h, l; split4(v, h, l);
        reinterpret_cast<float4*>(g_xhi)[j] = h;
        reinterpret_cast<float4*>(g_xlo)[j] = l;
    }
}

// ---------------- histogram (4 edges/thread) ----------------
__global__ void k_hist(const int* __restrict__ ei) {
    int t = blockIdx.x * blockDim.x + threadIdx.x;
    int4 d4 = reinterpret_cast<const int4*>(ei + E_EDGES)[t];
    atomicAdd(&g_cnt[d4.x], 1);
    atomicAdd(&g_cnt[d4.y], 1);
    atomicAdd(&g_cnt[d4.z], 1);
    atomicAdd(&g_cnt[d4.w], 1);
}

// ---------------- single-block prefix scan ----------------
__global__ void __launch_bounds__(1024) k_scan() {
    __shared__ int sp[1024];
    const int t = threadIdx.x;
    const int base = t * 20;
    int local[20];
    int s = 0;
#pragma unroll
    for (int i = 0; i < 20; i++) {
        int idx = base + i;
        int c = (idx < N_NODES) ? g_cnt[idx] : 0;
        local[i] = s;
        s += c;
    }
    sp[t] = s;
    __syncthreads();
    for (int off = 1; off < 1024; off <<= 1) {
        int add = (t >= off) ? sp[t - off] : 0;
        __syncthreads();
        sp[t] += add;
        __syncthreads();
    }
    int excl = (t > 0) ? sp[t - 1] : 0;
#pragma unroll
    for (int i = 0; i < 20; i++) {
        int idx = base + i;
        if (idx < N_NODES) {
            int o = excl + local[i];
            g_off[idx] = o;
            g_cur[idx] = o;
        }
    }
}

// ---------------- bucket (4 edges/thread) ----------------
__global__ void k_bucket(const int* __restrict__ ei, const float* __restrict__ ew) {
    int t = blockIdx.x * blockDim.x + threadIdx.x;
    int4  s4 = reinterpret_cast<const int4*>(ei)[t];
    int4  d4 = reinterpret_cast<const int4*>(ei + E_EDGES)[t];
    float4 w4 = reinterpret_cast<const float4*>(ew)[t];
    int p0 = atomicAdd(&g_cur[d4.x], 1);
    int p1 = atomicAdd(&g_cur[d4.y], 1);
    int p2 = atomicAdd(&g_cur[d4.z], 1);
    int p3 = atomicAdd(&g_cur[d4.w], 1);
    g_edges[p0] = make_int2(s4.x, __float_as_int(w4.x));
    g_edges[p1] = make_int2(s4.y, __float_as_int(w4.y));
    g_edges[p2] = make_int2(s4.z, __float_as_int(w4.z));
    g_edges[p3] = make_int2(s4.w, __float_as_int(w4.w));
}

// ---------------- gather-max: one warp per node; writes hi/lo agg ----------------
__global__ void __launch_bounds__(256) k_gather(const float* __restrict__ x) {
    int nid = blockIdx.x * 8 + (threadIdx.x >> 5);
    int lane = threadIdx.x & 31;
    if (nid >= N_NODES) return;
    int start = g_off[nid];
    int cnt = g_cnt[nid];
    int end = start + cnt;
    float4 m = make_float4(-INFINITY, -INFINITY, -INFINITY, -INFINITY);
    int e = start;
    for (; e + 3 < end; e += 4) {
        int2 r0 = g_edges[e + 0];
        int2 r1 = g_edges[e + 1];
        int2 r2 = g_edges[e + 2];
        int2 r3 = g_edges[e + 3];
        float4 x0 = *reinterpret_cast<const float4*>(&x[r0.x * D + lane * 4]);
        float4 x1 = *reinterpret_cast<const float4*>(&x[r1.x * D + lane * 4]);
        float4 x2 = *reinterpret_cast<const float4*>(&x[r2.x * D + lane * 4]);
        float4 x3 = *reinterpret_cast<const float4*>(&x[r3.x * D + lane * 4]);
        float w0 = __int_as_float(r0.y), w1 = __int_as_float(r1.y);
        float w2 = __int_as_float(r2.y), w3 = __int_as_float(r3.y);
        m.x = fmaxf(fmaxf(m.x, w0 * x0.x), fmaxf(w1 * x1.x, fmaxf(w2 * x2.x, w3 * x3.x)));
        m.y = fmaxf(fmaxf(m.y, w0 * x0.y), fmaxf(w1 * x1.y, fmaxf(w2 * x2.y, w3 * x3.y)));
        m.z = fmaxf(fmaxf(m.z, w0 * x0.z), fmaxf(w1 * x1.z, fmaxf(w2 * x2.z, w3 * x3.z)));
        m.w = fmaxf(fmaxf(m.w, w0 * x0.w), fmaxf(w1 * x1.w, fmaxf(w2 * x2.w, w3 * x3.w)));
    }
    for (; e < end; e++) {
        int2 r = g_edges[e];
        float w = __int_as_float(r.y);
        float4 xr = *reinterpret_cast<const float4*>(&x[r.x * D + lane * 4]);
        m.x = fmaxf(m.x, w * xr.x); m.y = fmaxf(m.y, w * xr.y);
        m.z = fmaxf(m.z, w * xr.z); m.w = fmaxf(m.w, w * xr.w);
    }
    if (cnt == 0) m = make_float4(0.f, 0.f, 0.f, 0.f);   // PyG empty-segment fill
    float4 h, l; split4(m, h, l);
    int o4 = (nid * D) / 4 + lane;
    reinterpret_cast<float4*>(g_agghi)[o4] = h;
    reinterpret_cast<float4*>(g_agglo)[o4] = l;
}

// ---------------- copy edge_weight to output tail ----------------
__global__ void k_copy_ew(const float* __restrict__ ew, float* __restrict__ dst) {
    int i = blockIdx.x * blockDim.x + threadIdx.x;
    if (i < E_EDGES / 4)
        reinterpret_cast<float4*>(dst)[i] = reinterpret_cast<const float4*>(ew)[i];
}

// ---------------- fused wmma-TF32 GEMM + bias + GELU + skip + LayerNorm ----------------
// MODE 0: acc = agg@Wrel^T + x@Wroot^T; skip = x (arg);  dst = g_h (+hi/lo)
// MODE 1: acc = h@linW^T;               skip = g_h;      dst = out (arg)
// ALL device-global operands are referenced directly in device code (never
// passed as host-side kernel args). Block tile 64x128; 8 warps:
// wm=wid>>1 (16 rows), wn=wid&1 (64 cols = 4 x m16n16). wmma owns fragment layouts.
// A row_major ldm=D from padded globals; B col_major ldm=D (W[n][k] == col-major B(k,n)).
template<int MODE>
__global__ void __launch_bounds__(256)
k_fused(const float* __restrict__ skiparg,   // x (mode0) / unused (mode1)
        const float* __restrict__ bias,
        const float* __restrict__ gamma,
        const float* __restrict__ beta,
        float* __restrict__ outarg) {        // unused (mode0) / out (mode1)
    __shared__ float s_out[64 * 136];

    const float* Ahi = (MODE == 0) ? g_agghi : g_hhi;
    const float* Alo = (MODE == 0) ? g_agglo : g_hlo;
    const float* W1hi = (MODE == 0) ? g_Wrelhi : g_linhi;
    const float* W1lo = (MODE == 0) ? g_Wrello : g_linlo;
    const float* skip = (MODE == 0) ? skiparg : g_h;
    float* dst = (MODE == 0) ? g_h : outarg;

    const int tid = threadIdx.x;
    const int wid = tid >> 5;
    const int lane = tid & 31;
    const int wm = wid >> 1;
    const int wn = wid & 1;
    const int n0 = blockIdx.x * 64;
    const int arow = n0 + wm * 16;       // safe: padded operand arrays (N_PAD)

    wmma::fragment<wmma::accumulator, 16, 16, 8, float> acc[4];
#pragma unroll
    for (int ct = 0; ct < 4; ct++) wmma::fill_fragment(acc[ct], 0.0f);

#pragma unroll 1
    for (int k0 = 0; k0 < D; k0 += 8) {
        wmma::fragment<wmma::matrix_a, 16, 16, 8, wmma::precision::tf32, wmma::row_major> ah, al, xh, xl;
        wmma::load_matrix_sync(ah, Ahi + arow * D + k0, D);
        wmma::load_matrix_sync(al, Alo + arow * D + k0, D);
#pragma unroll
        for (int e = 0; e < ah.num_elements; e++) {
            ah.x[e] = wmma::__float_to_tf32(ah.x[e]);
            al.x[e] = wmma::__float_to_tf32(al.x[e]);
        }
        if constexpr (MODE == 0) {
            wmma::load_matrix_sync(xh, g_xhi + arow * D + k0, D);
            wmma::load_matrix_sync(xl, g_xlo + arow * D + k0, D);
#pragma unroll
            for (int e = 0; e < xh.num_elements; e++) {
                xh.x[e] = wmma::__float_to_tf32(xh.x[e]);
                xl.x[e] = wmma::__float_to_tf32(xl.x[e]);
            }
        }
#pragma unroll
        for (int ct = 0; ct < 4; ct++) {
            const int col = wn * 64 + ct * 16;
            wmma::fragment<wmma::matrix_b, 16, 16, 8, wmma::precision::tf32, wmma::col_major> bh, bl;
            wmma::load_matrix_sync(bh, W1hi + col * D + k0, D);
            wmma::load_matrix_sync(bl, W1lo + col * D + k0, D);
#pragma unroll
            for (int e = 0; e < bh.num_elements; e++) {
                bh.x[e] = wmma::__float_to_tf32(bh.x[e]);
                bl.x[e] = wmma::__float_to_tf32(bl.x[e]);
            }
            wmma::mma_sync(acc[ct], ah, bh, acc[ct]);
            wmma::mma_sync(acc[ct], ah, bl, acc[ct]);
            wmma::mma_sync(acc[ct], al, bh, acc[ct]);
            if constexpr (MODE == 0) {
                wmma::fragment<wmma::matrix_b, 16, 16, 8, wmma::precision::tf32, wmma::col_major> uh, ul;
                wmma::load_matrix_sync(uh, g_Wroothi + col * D + k0, D);
                wmma::load_matrix_sync(ul, g_Wrootlo + col * D + k0, D);
#pragma unroll
                for (int e = 0; e < uh.num_elements; e++) {
                    uh.x[e] = wmma::__float_to_tf32(uh.x[e]);
                    ul.x[e] = wmma::__float_to_tf32(ul.x[e]);
                }
                wmma::mma_sync(acc[ct], xh, uh, acc[ct]);
                wmma::mma_sync(acc[ct], xh, ul, acc[ct]);
                wmma::mma_sync(acc[ct], xl, uh, acc[ct]);
            }
        }
    }

    // dump accumulators to smem (wmma owns the layout)
#pragma unroll
    for (int ct = 0; ct < 4; ct++)
        wmma::store_matrix_sync(&s_out[(wm * 16) * 136 + wn * 64 + ct * 16],
                                acc[ct], 136, wmma::mem_row_major);
    __syncthreads();

    // ---- LN epilogue: each warp owns 8 rows; lane covers 4 consecutive cols ----
    const int c0 = lane * 4;
    float4 bb = *reinterpret_cast<const float4*>(&bias[c0]);
    float4 gm = *reinterpret_cast<const float4*>(&gamma[c0]);
    float4 bt = *reinterpret_cast<const float4*>(&beta[c0]);
#pragma unroll
    for (int r = 0; r < 8; r++) {
        int row = wid * 8 + r;
        int gn = n0 + row;
        int gns = min(gn, N_NODES - 1);   // clamp: skip may be the unpadded input x
        float4 v = *reinterpret_cast<const float4*>(&s_out[row * 136 + c0]);
        float4 sk = *reinterpret_cast<const float4*>(&skip[gns * D + c0]);
        float g0 = gelu_exact(v.x + bb.x) + sk.x;
        float g1 = gelu_exact(v.y + bb.y) + sk.y;
        float g2 = gelu_exact(v.z + bb.z) + sk.z;
        float g3 = gelu_exact(v.w + bb.w) + sk.w;
        float s1 = g0 + g1 + g2 + g3;
        float s2 = g0 * g0 + g1 * g1 + g2 * g2 + g3 * g3;
#pragma unroll
        for (int off = 16; off >= 1; off >>= 1) {
            s1 += __shfl_xor_sync(0xFFFFFFFFu, s1, off);
            s2 += __shfl_xor_sync(0xFFFFFFFFu, s2, off);
        }
        float mu = s1 * (1.0f / 128.0f);
        float var = fmaxf(s2 * (1.0f / 128.0f) - mu * mu, 0.0f);
        float rs = rsqrtf(var + 1e-5f);
        if (gn < N_NODES) {
            float4 o;
            o.x = (g0 - mu) * rs * gm.x + bt.x;
            o.y = (g1 - mu) * rs * gm.y + bt.y;
            o.z = (g2 - mu) * rs * gm.z + bt.z;
            o.w = (g3 - mu) * rs * gm.w + bt.w;
            *reinterpret_cast<float4*>(&dst[gn * D + c0]) = o;
            if constexpr (MODE == 0) {
                float4 h, l; split4(o, h, l);
                *reinterpret_cast<float4*>(&g_hhi[gn * D + c0]) = h;
                *reinterpret_cast<float4*>(&g_hlo[gn * D + c0]) = l;
            }
        }
    }
}

extern "C" void kernel_launch(void* const* d_in, const int* in_sizes, int n_in,
                              void* d_out, int out_size) {
    const float* x     = (const float*)d_in[0];
    const int*   ei    = (const int*)d_in[1];      // int32 (JAX x64 disabled)
    const float* ew    = (const float*)d_in[2];
    const float* Wrel  = (const float*)d_in[3];
    const float* brel  = (const float*)d_in[4];
    const float* Wroot = (const float*)d_in[5];
    const float* linW  = (const float*)d_in[6];
    const float* linb  = (const float*)d_in[7];
    const float* gamma = (const float*)d_in[8];
    const float* beta  = (const float*)d_in[9];
    float* out = (float*)d_out;

    // prep: zero hist + hi/lo splits of weights and x
    k_prep<<<79 + 48 + 2500, 256>>>(x, Wrel, Wroot, linW);
    // counting-sort edges by dst, then gather-max (R5-proven chain)
    k_hist<<<E_EDGES / 4 / 256, 256>>>(ei);
    k_scan<<<1, 1024>>>();
    k_bucket<<<E_EDGES / 4 / 256, 256>>>(ei, ew);
    k_gather<<<(N_NODES + 7) / 8, 256>>>(x);
    // layer 1: agg@Wrel^T + b + x@Wroot^T -> gelu + x -> LN -> g_h (+ hi/lo)
    k_fused<0><<<(N_NODES + 63) / 64, 256>>>(x, brel, gamma, beta, nullptr);
    // layer 2: h@linW^T + b -> gelu + h -> LN -> out
    k_fused<1><<<(N_NODES + 63) / 64, 256>>>(nullptr, linb, gamma, beta, out);
    // edge_weight pass-through
    if (out_size >= E_EDGES) {
        float* ew_dst = out + (out_size - E_EDGES);
        k_copy_ew<<<(E_EDGES / 4 + 255) / 256, 256>>>(ew, ew_dst);
    }
}

// round 17
// speedup vs baseline: 1.5460x; 1.5460x over previous
#include <cuda_runtime.h>
#include <mma.h>
#include <math.h>

using namespace nvcuda;

#define N_NODES 20000
#define D 128
#define E_EDGES 640000

// ---- scratch (device globals; referenced ONLY from device code — never passed
// as host-side kernel args: host shadow address reads as zeros via ATS) ----
__device__ float g_aggf[N_NODES * D];   // max-aggregated messages (0 if empty)
__device__ float g_h[N_NODES * D];      // layer-1 output
__device__ int   g_cnt[N_NODES];
__device__ int   g_off[N_NODES];
__device__ int   g_cur[N_NODES];
__device__ int2  g_edges[E_EDGES];

__device__ __forceinline__ float gelu_exact(float v) {
    return 0.5f * v * (1.0f + erff(v * 0.70710678118654752f));
}
__device__ __forceinline__ float tf32_hi(float v) {
    return __uint_as_float(__float_as_uint(v) & 0xFFFFE000u);
}

// ---- cp.async helpers ----
__device__ __forceinline__ void cpa16(void* dst, const void* src) {
    unsigned d = (unsigned)__cvta_generic_to_shared(dst);
    asm volatile("cp.async.cg.shared.global [%0], [%1], 16;\n" :: "r"(d), "l"(src));
}
__device__ __forceinline__ void cpa_commit() { asm volatile("cp.async.commit_group;\n"); }
__device__ __forceinline__ void cpa_wait0()  { asm volatile("cp.async.wait_group 0;\n" ::: "memory"); }

// ---------------- zero histogram ----------------
__global__ void k_zero_cnt() {
    int i = blockIdx.x * blockDim.x + threadIdx.x;
    if (i < N_NODES) g_cnt[i] = 0;
}

// ---------------- histogram (4 edges/thread) ----------------
__global__ void k_hist(const int* __restrict__ ei) {
    int t = blockIdx.x * blockDim.x + threadIdx.x;
    int4 d4 = reinterpret_cast<const int4*>(ei + E_EDGES)[t];
    atomicAdd(&g_cnt[d4.x], 1);
    atomicAdd(&g_cnt[d4.y], 1);
    atomicAdd(&g_cnt[d4.z], 1);
    atomicAdd(&g_cnt[d4.w], 1);
}

// ---------------- single-block prefix scan ----------------
__global__ void __launch_bounds__(1024) k_scan() {
    __shared__ int sp[1024];
    const int t = threadIdx.x;
    const int base = t * 20;
    int local[20];
    int s = 0;
#pragma unroll
    for (int i = 0; i < 20; i++) {
        int idx = base + i;
        int c = (idx < N_NODES) ? g_cnt[idx] : 0;
        local[i] = s;
        s += c;
    }
    sp[t] = s;
    __syncthreads();
    for (int off = 1; off < 1024; off <<= 1) {
        int add = (t >= off) ? sp[t - off] : 0;
        __syncthreads();
        sp[t] += add;
        __syncthreads();
    }
    int excl = (t > 0) ? sp[t - 1] : 0;
#pragma unroll
    for (int i = 0; i < 20; i++) {
        int idx = base + i;
        if (idx < N_NODES) {
            int o = excl + local[i];
            g_off[idx] = o;
            g_cur[idx] = o;
        }
    }
}

// ---------------- bucket (4 edges/thread) ----------------
__global__ void k_bucket(const int* __restrict__ ei, const float* __restrict__ ew) {
    int t = blockIdx.x * blockDim.x + threadIdx.x;
    int4  s4 = reinterpret_cast<const int4*>(ei)[t];
    int4  d4 = reinterpret_cast<const int4*>(ei + E_EDGES)[t];
    float4 w4 = reinterpret_cast<const float4*>(ew)[t];
    int p0 = atomicAdd(&g_cur[d4.x], 1);
    int p1 = atomicAdd(&g_cur[d4.y], 1);
    int p2 = atomicAdd(&g_cur[d4.z], 1);
    int p3 = atomicAdd(&g_cur[d4.w], 1);
    g_edges[p0] = make_int2(s4.x, __float_as_int(w4.x));
    g_edges[p1] = make_int2(s4.y, __float_as_int(w4.y));
    g_edges[p2] = make_int2(s4.z, __float_as_int(w4.z));
    g_edges[p3] = make_int2(s4.w, __float_as_int(w4.w));
}

// ---------------- gather-max: one warp per node (f32 agg; R5-proven) ----------------
__global__ void __launch_bounds__(256) k_gather(const float* __restrict__ x) {
    int nid = blockIdx.x * 8 + (threadIdx.x >> 5);
    int lane = threadIdx.x & 31;
    if (nid >= N_NODES) return;
    int start = g_off[nid];
    int cnt = g_cnt[nid];
    int end = start + cnt;
    float4 m = make_float4(-INFINITY, -INFINITY, -INFINITY, -INFINITY);
    int e = start;
    for (; e + 3 < end; e += 4) {
        int2 r0 = g_edges[e + 0];
        int2 r1 = g_edges[e + 1];
        int2 r2 = g_edges[e + 2];
        int2 r3 = g_edges[e + 3];
        float4 x0 = *reinterpret_cast<const float4*>(&x[r0.x * D + lane * 4]);
        float4 x1 = *reinterpret_cast<const float4*>(&x[r1.x * D + lane * 4]);
        float4 x2 = *reinterpret_cast<const float4*>(&x[r2.x * D + lane * 4]);
        float4 x3 = *reinterpret_cast<const float4*>(&x[r3.x * D + lane * 4]);
        float w0 = __int_as_float(r0.y), w1 = __int_as_float(r1.y);
        float w2 = __int_as_float(r2.y), w3 = __int_as_float(r3.y);
        m.x = fmaxf(fmaxf(m.x, w0 * x0.x), fmaxf(w1 * x1.x, fmaxf(w2 * x2.x, w3 * x3.x)));
        m.y = fmaxf(fmaxf(m.y, w0 * x0.y), fmaxf(w1 * x1.y, fmaxf(w2 * x2.y, w3 * x3.y)));
        m.z = fmaxf(fmaxf(m.z, w0 * x0.z), fmaxf(w1 * x1.z, fmaxf(w2 * x2.z, w3 * x3.z)));
        m.w = fmaxf(fmaxf(m.w, w0 * x0.w), fmaxf(w1 * x1.w, fmaxf(w2 * x2.w, w3 * x3.w)));
    }
    for (; e < end; e++) {
        int2 r = g_edges[e];
        float w = __int_as_float(r.y);
        float4 xr = *reinterpret_cast<const float4*>(&x[r.x * D + lane * 4]);
        m.x = fmaxf(m.x, w * xr.x); m.y = fmaxf(m.y, w * xr.y);
        m.z = fmaxf(m.z, w * xr.z); m.w = fmaxf(m.w, w * xr.w);
    }
    if (cnt == 0) m = make_float4(0.f, 0.f, 0.f, 0.f);   // PyG empty-segment fill
    *reinterpret_cast<float4*>(&g_aggf[nid * D + lane * 4]) = m;
}

// ---------------- copy edge_weight to output tail ----------------
__global__ void k_copy_ew(const float* __restrict__ ew, float* __restrict__ dst) {
    int i = blockIdx.x * blockDim.x + threadIdx.x;
    if (i < E_EDGES / 4)
        reinterpret_cast<float4*>(dst)[i] = reinterpret_cast<const float4*>(ew)[i];
}

// ---- load a tf32 fragment pair (hi, lo) from an f32 smem tile ----
template<typename Frag>
__device__ __forceinline__ void load_split(Frag& fh, Frag& fl, const float* p, int ldm) {
    wmma::load_matrix_sync(fh, p, ldm);
#pragma unroll
    for (int e = 0; e < fh.num_elements; e++) {
        float v = fh.x[e];
        float h = tf32_hi(v);
        fh.x[e] = wmma::__float_to_tf32(h);
        fl.x[e] = wmma::__float_to_tf32(v - h);
    }
}

// ---------------- fused wmma-TF32 GEMM + bias + GELU + skip + LayerNorm ----------------
// MODE 0: acc = agg@Wrel^T + x@Wroot^T; skip = x (arg);  dst = g_h
// MODE 1: acc = h@linW^T;               skip = g_h;      dst = out (arg)
// Block tile 64 x 128; 8 warps: wm=wid>>1 (16 rows), wn=wid&1 (64 cols = 4 x m16n16).
// f32 tiles staged in smem via cp.async (k-tiles of 32, stride 36); tf32 hi/lo split
// happens in registers on loaded fragments. wmma owns all fragment layouts.
template<int MODE>
__global__ void __launch_bounds__(256)
k_fused(const float* __restrict__ Wrel,   // mode0; unused mode1
        const float* __restrict__ Wroot,  // mode0; unused mode1
        const float* __restrict__ linW,   // mode1; unused mode0
        const float* __restrict__ skiparg,
        const float* __restrict__ bias,
        const float* __restrict__ gamma,
        const float* __restrict__ beta,
        float* __restrict__ outarg) {
    extern __shared__ __align__(16) float sm[];
    float* sA  = sm;                                   // [64][36]
    float* sX  = sm + 2304;                            // [64][36]  (m0 only)
    float* sW1 = (MODE == 0) ? sm + 4608 : sm + 2304;  // [128][36]
    float* sW2 = sW1 + 4608;                           // [128][36] (m0 only)
    float* s_out = sm;                                 // [64][136] reuse post-mma

    const float* Asrc = (MODE == 0) ? g_aggf : g_h;
    const float* W1   = (MODE == 0) ? Wrel : linW;
    const float* skip = (MODE == 0) ? skiparg : g_h;
    float* dst = (MODE == 0) ? g_h : outarg;

    const int tid = threadIdx.x;
    const int wid = tid >> 5;
    const int lane = tid & 31;
    const int wm = wid >> 1;
    const int wn = wid & 1;
    const int n0 = blockIdx.x * 64;

    typedef wmma::fragment<wmma::matrix_a, 16, 16, 8, wmma::precision::tf32, wmma::row_major> FragA;
    typedef wmma::fragment<wmma::matrix_b, 16, 16, 8, wmma::precision::tf32, wmma::col_major> FragB;

    wmma::fragment<wmma::accumulator, 16, 16, 8, float> acc[4];
#pragma unroll
    for (int ct = 0; ct < 4; ct++) wmma::fill_fragment(acc[ct], 0.0f);

#pragma unroll 1
    for (int kt = 0; kt < 4; kt++) {
        const int k0 = kt * 32;
        // A (and X) tiles: 64 rows x 32 k
#pragma unroll
        for (int i = 0; i < 2; i++) {
            int idx = tid + i * 256;
            int r = idx >> 3, c = idx & 7;
            int gn = min(n0 + r, N_NODES - 1);
            cpa16(sA + r * 36 + c * 4, Asrc + gn * D + k0 + c * 4);
            if constexpr (MODE == 0)
                cpa16(sX + r * 36 + c * 4, skiparg + gn * D + k0 + c * 4);
        }
        // W tiles: 128 rows x 32 k
#pragma unroll
        for (int i = 0; i < 4; i++) {
            int idx = tid + i * 256;
            int d = idx >> 3, c = idx & 7;
            cpa16(sW1 + d * 36 + c * 4, W1 + d * D + k0 + c * 4);
            if constexpr (MODE == 0)
                cpa16(sW2 + d * 36 + c * 4, Wroot + d * D + k0 + c * 4);
        }
        cpa_commit();
        cpa_wait0();
        __syncthreads();

#pragma unroll
        for (int ks = 0; ks < 4; ks++) {
            const float* aBase = sA + (wm * 16) * 36 + ks * 8;
            FragA ah, al, xh, xl;
            load_split(ah, al, aBase, 36);
            if constexpr (MODE == 0)
                load_split(xh, xl, sX + (wm * 16) * 36 + ks * 8, 36);
#pragma unroll
            for (int ct = 0; ct < 4; ct++) {
                const int col = wn * 64 + ct * 16;
                FragB bh, bl;
                load_split(bh, bl, sW1 + col * 36 + ks * 8, 36);
                wmma::mma_sync(acc[ct], ah, bh, acc[ct]);
                wmma::mma_sync(acc[ct], ah, bl, acc[ct]);
                wmma::mma_sync(acc[ct], al, bh, acc[ct]);
                if constexpr (MODE == 0) {
                    FragB uh, ul;
                    load_split(uh, ul, sW2 + col * 36 + ks * 8, 36);
                    wmma::mma_sync(acc[ct], xh, uh, acc[ct]);
                    wmma::mma_sync(acc[ct], xh, ul, acc[ct]);
                    wmma::mma_sync(acc[ct], xl, uh, acc[ct]);
                }
            }
        }
        __syncthreads();
    }

    // dump accumulators to smem (wmma owns the layout)
#pragma unroll
    for (int ct = 0; ct < 4; ct++)
        wmma::store_matrix_sync(&s_out[(wm * 16) * 136 + wn * 64 + ct * 16],
                                acc[ct], 136, wmma::mem_row_major);
    __syncthreads();

    // ---- LN epilogue: each warp owns 8 rows; lane covers 4 consecutive cols ----
    const int c0 = lane * 4;
    float4 bb = *reinterpret_cast<const float4*>(&bias[c0]);
    float4 gm = *reinterpret_cast<const float4*>(&gamma[c0]);
    float4 bt = *reinterpret_cast<const float4*>(&beta[c0]);
#pragma unroll
    for (int r = 0; r < 8; r++) {
        int row = wid * 8 + r;
        int gn = n0 + row;
        int gns = min(gn, N_NODES - 1);
        float4 v = *reinterpret_cast<const float4*>(&s_out[row * 136 + c0]);
        float4 sk = *reinterpret_cast<const float4*>(&skip[gns * D + c0]);
        float g0 = gelu_exact(v.x + bb.x) + sk.x;
        float g1 = gelu_exact(v.y + bb.y) + sk.y;
        float g2 = gelu_exact(v.z + bb.z) + sk.z;
        float g3 = gelu_exact(v.w + bb.w) + sk.w;
        float s1 = g0 + g1 + g2 + g3;
        float s2 = g0 * g0 + g1 * g1 + g2 * g2 + g3 * g3;
#pragma unroll
        for (int off = 16; off >= 1; off >>= 1) {
            s1 += __shfl_xor_sync(0xFFFFFFFFu, s1, off);
            s2 += __shfl_xor_sync(0xFFFFFFFFu, s2, off);
        }
        float mu = s1 * (1.0f / 128.0f);
        float var = fmaxf(s2 * (1.0f / 128.0f) - mu * mu, 0.0f);
        float rs = rsqrtf(var + 1e-5f);
        if (gn < N_NODES) {
            float4 o;
            o.x = (g0 - mu) * rs * gm.x + bt.x;
            o.y = (g1 - mu) * rs * gm.y + bt.y;
            o.z = (g2 - mu) * rs * gm.z + bt.z;
            o.w = (g3 - mu) * rs * gm.w + bt.w;
            *reinterpret_cast<float4*>(&dst[gn * D + c0]) = o;
        }
    }
}

extern "C" void kernel_launch(void* const* d_in, const int* in_sizes, int n_in,
                              void* d_out, int out_size) {
    const float* x     = (const float*)d_in[0];
    const int*   ei    = (const int*)d_in[1];      // int32 (JAX x64 disabled)
    const float* ew    = (const float*)d_in[2];
    const float* Wrel  = (const float*)d_in[3];
    const float* brel  = (const float*)d_in[4];
    const float* Wroot = (const float*)d_in[5];
    const float* linW  = (const float*)d_in[6];
    const float* linb  = (const float*)d_in[7];
    const float* gamma = (const float*)d_in[8];
    const float* beta  = (const float*)d_in[9];
    float* out = (float*)d_out;

    const int SMEM0 = 64 * 136 * 4;                      // s_out dominates mode0 GEMM tiles? no:
    const int SMEM_G0 = (2304 + 2304 + 4608 + 4608) * 4; // 55296 B (mode0 GEMM tiles)
    const int SMEM_M0 = SMEM_G0 > SMEM0 ? SMEM_G0 : SMEM0;
    const int SMEM_M1 = SMEM0;                           // mode1: s_out (34816) > tiles (27648)
    static bool attr_done = false;
    if (!attr_done) {
        cudaFuncSetAttribute(k_fused<0>, cudaFuncAttributeMaxDynamicSharedMemorySize, SMEM_M0);
        cudaFuncSetAttribute(k_fused<1>, cudaFuncAttributeMaxDynamicSharedMemorySize, SMEM_M1);
        attr_done = true;
    }

    // counting-sort edges by dst, then gather-max (R5-proven chain)
    k_zero_cnt<<<(N_NODES + 255) / 256, 256>>>();
    k_hist<<<E_EDGES / 4 / 256, 256>>>(ei);
    k_scan<<<1, 1024>>>();
    k_bucket<<<E_EDGES / 4 / 256, 256>>>(ei, ew);
    k_gather<<<(N_NODES + 7) / 8, 256>>>(x);
    // layer 1: agg@Wrel^T + b + x@Wroot^T -> gelu + x -> LN -> g_h
    k_fused<0><<<(N_NODES + 63) / 64, 256, SMEM_M0>>>(Wrel, Wroot, nullptr, x, brel, gamma, beta, nullptr);
    // layer 2: h@linW^T + b -> gelu + h -> LN -> out
    k_fused<1><<<(N_NODES + 63) / 64, 256, SMEM_M1>>>(nullptr, nullptr, linW, nullptr, linb, gamma, beta, out);
    // edge_weight pass-through
    if (out_size >= E_EDGES) {
        float* ew_dst = out + (out_size - E_EDGES);
        k_copy_ew<<<(E_EDGES / 4 + 255) / 256, 256>>>(ew, ew_dst);
    }
}